// round 5
// baseline (speedup 1.0000x reference)
#include <cuda_runtime.h>
#include <cuda_bf16.h>
#include <cstdint>
#include <cstddef>

// Problem constants
#define BB 16
#define CC 64
#define HH 256
#define WW 256
#define MM 12
// number of (b, channel) planes
#define NBI (BB*CC)          // 1024
#define NPAIR (24*MM)        // 288 mode pairs (12 top kx + 12 bottom kx) x 12 ky

// ---------------- device scratch (static, no allocation) ----------------
__device__ float2 g_Xh[(size_t)NBI * 13 * WW];          // h-DFT result, k=0..12  (~27 MB)
__device__ float2 g_Xf[(size_t)NPAIR * NBI];            // modes  [pair][b*C+i]   (~2.4 MB)
__device__ float2 g_Yf[(size_t)NBI * NPAIR];            // mixed  [b*C+o][pair]   (~2.4 MB)
__device__ float2 g_Z[(size_t)BB * HH * CC * MM];       // [b][h][o][ky]          (~25 MB)
__device__ float  g_ctab[256];                          // cos(2*pi*t/256)
__device__ float  g_sum[CC], g_sumsq[CC];

// sin(2*pi*m/256) = cos(2*pi*(m+192)/256)
#define SIDX(m) (((m) + 192) & 255)

// ---------------- init: twiddle table + zero stats ----------------
__global__ void k_init() {
    int t = threadIdx.x;
    g_ctab[t] = cospif((float)t * (1.0f / 128.0f));   // cos(2*pi*t/256)
    if (t < CC) { g_sum[t] = 0.f; g_sumsq[t] = 0.f; }
}

// ---------------- K1: DFT along h, k = 0..12, uses h <-> 256-h symmetry ----------------
__global__ void __launch_bounds__(256) k_dft_h(const float* __restrict__ x) {
    int bi = blockIdx.x;          // b*C + i
    int w  = threadIdx.x;         // 0..255
    __shared__ float ct[256];
    ct[w] = g_ctab[w];
    __syncthreads();

    const float* xp = x + (size_t)bi * (HH * WW) + w;
    float x0   = xp[0];
    float x128 = xp[(size_t)128 * WW];

    float aR[13], aI[13];
#pragma unroll
    for (int k = 0; k < 13; k++) {
        aR[k] = x0 + ((k & 1) ? -x128 : x128);   // cos(pi*k) = (-1)^k, sin = 0
        aI[k] = 0.f;
    }
    for (int h = 1; h < 128; h++) {
        float xa = xp[(size_t)h * WW];
        float xb = xp[(size_t)(256 - h) * WW];
        float sm = xa + xb;
        float df = xa - xb;
        int m = 0;
#pragma unroll
        for (int k = 0; k < 13; k++) {
            float c = ct[m];
            float s = ct[SIDX(m)];
            aR[k] = fmaf(sm,  c, aR[k]);     // sum_h x*cos(kh)
            aI[k] = fmaf(-df, s, aI[k]);     // -sum_h x*sin(kh)
            m = (m + h) & 255;
        }
    }
#pragma unroll
    for (int k = 0; k < 13; k++)
        g_Xh[((size_t)bi * 13 + k) * WW + w] = make_float2(aR[k], aI[k]);
}

// ---------------- K2: DFT along w to ky = 0..11 for 24 kx rows ----------------
// pair index p = kxidx*12 + ky; kxidx 0..11 = top rows (kx=k), 12..23 = bottom (kx=244+m, uses conj(Xh[12-m]))
__global__ void __launch_bounds__(NPAIR) k_dft_w() {
    int bi = blockIdx.x;
    __shared__ float2 Xs[13 * WW];   // 26 KB
    __shared__ float  ct[256];
    int t = threadIdx.x;             // 0..287
    for (int idx = t; idx < 13 * WW; idx += NPAIR)
        Xs[idx] = g_Xh[(size_t)bi * 13 * WW + idx];
    if (t < 256) ct[t] = g_ctab[t];
    __syncthreads();

    int kxidx = t / MM, ky = t % MM;
    bool bot = (kxidx >= 12);
    int  krow = bot ? (24 - kxidx) : kxidx;   // 12-m for bottom
    float sgn = bot ? -1.f : 1.f;             // conjugate for bottom

    float aR = 0.f, aI = 0.f;
    int m = 0;
    for (int w = 0; w < WW; w++) {
        float2 v  = Xs[krow * WW + w];
        float  vi = v.y * sgn;
        float c = ct[m];
        float s = ct[SIDX(m)];
        // (vr + i*vi) * (c - i*s)
        aR = fmaf(v.x, c, aR); aR = fmaf(vi,  s, aR);
        aI = fmaf(vi,  c, aI); aI = fmaf(-v.x, s, aI);
        m = (m + ky) & 255;
    }
    g_Xf[(size_t)t * NBI + bi] = make_float2(aR, aI);
}

// ---------------- K3: channel mixing, one block per (kx,ky) mode pair ----------------
__global__ void __launch_bounds__(256) k_mix(const float* __restrict__ w1,
                                             const float* __restrict__ w2) {
    int pair = blockIdx.x;            // 0..287
    int kxidx = pair / MM, ky = pair % MM;
    const float* wsrc = (kxidx < 12) ? w1 : w2;
    int kxrel = (kxidx < 12) ? kxidx : (kxidx - 12);

    __shared__ float2 As[BB * CC];    // [b][i]  8 KB
    __shared__ float2 Ws[CC * CC];    // [i][o]  32 KB
    int t = threadIdx.x;

    for (int idx = t; idx < BB * CC; idx += 256)
        As[idx] = g_Xf[(size_t)pair * NBI + idx];

    size_t wbase = (size_t)(kxrel * MM + ky) * 2;
    for (int idx = t; idx < CC * CC; idx += 256) {
        int i = idx >> 6, o = idx & 63;
        size_t off = (size_t)i * (CC * MM * MM * 2) + (size_t)o * (MM * MM * 2) + wbase;
        Ws[idx] = make_float2(wsrc[off], wsrc[off + 1]);
    }
    __syncthreads();

    int o  = t & 63;
    int bq = t >> 6;  // 0..3 -> 4 batches each
    float aR[4] = {0, 0, 0, 0}, aI[4] = {0, 0, 0, 0};
    for (int i = 0; i < CC; i++) {
        float2 wv = Ws[i * CC + o];
#pragma unroll
        for (int j = 0; j < 4; j++) {
            float2 av = As[(bq * 4 + j) * CC + i];
            aR[j] = fmaf(av.x, wv.x, aR[j]); aR[j] = fmaf(-av.y, wv.y, aR[j]);
            aI[j] = fmaf(av.x, wv.y, aI[j]); aI[j] = fmaf(av.y,  wv.x, aI[j]);
        }
    }
#pragma unroll
    for (int j = 0; j < 4; j++) {
        int bi = (bq * 4 + j) * CC + o;
        g_Yf[(size_t)bi * NPAIR + pair] = make_float2(aR[j], aI[j]);
    }
}

// ---------------- K4: inverse DFT along h (24 modes -> 256 h), scale 1/(H*W) ----------------
__global__ void __launch_bounds__(256) k_inv_h() {
    int bi = blockIdx.x;            // b*C + o
    int b = bi >> 6, o = bi & 63;
    __shared__ float2 Ys[NPAIR];
    __shared__ float  ct[256];
    int h = threadIdx.x;
    for (int idx = h; idx < NPAIR; idx += 256)
        Ys[idx] = g_Yf[(size_t)bi * NPAIR + idx];
    ct[h] = g_ctab[h];
    __syncthreads();

    float cc[13], ss[13];
    {
        int m = 0;
#pragma unroll
        for (int k = 0; k < 13; k++) {
            cc[k] = ct[m]; ss[k] = ct[SIDX(m)];
            m = (m + h) & 255;
        }
    }
    const float scale = 1.0f / 65536.0f;
#pragma unroll
    for (int ky = 0; ky < MM; ky++) {
        float aR = 0.f, aI = 0.f;
#pragma unroll
        for (int k = 0; k < 12; k++) {          // top: e^{+i k theta_h}
            float2 v = Ys[k * MM + ky];
            aR = fmaf(v.x, cc[k], aR); aR = fmaf(-v.y, ss[k], aR);
            aI = fmaf(v.x, ss[k], aI); aI = fmaf( v.y, cc[k], aI);
        }
#pragma unroll
        for (int mm = 0; mm < 12; mm++) {       // bottom kx=244+mm: e^{-i (12-mm) theta_h}
            float2 v = Ys[(12 + mm) * MM + ky];
            float c = cc[12 - mm], s = ss[12 - mm];
            aR = fmaf(v.x, c, aR); aR = fmaf( v.y, s, aR);
            aI = fmaf(v.y, c, aI); aI = fmaf(-v.x, s, aI);
        }
        g_Z[(((size_t)(b * HH + h)) * CC + o) * MM + ky] = make_float2(aR * scale, aI * scale);
    }
}

// ---------------- K5: fused w-inverse (12 modes) + 1x1 conv + bias -> y in d_out ----------------
// grid: (wq=4, h=256, b=16), block 256 = (w 0..63, og 0..3); each thread 16 output channels
__global__ void __launch_bounds__(256) k_final(const float* __restrict__ x,
                                               const float* __restrict__ wc,
                                               const float* __restrict__ bc,
                                               float* __restrict__ out) {
    int wq = blockIdx.x, h = blockIdx.y, b = blockIdx.z;
    __shared__ float  xs[CC][64];      // [i][w] 16 KB
    __shared__ float4 wcs[CC][16];     // [o][i/4] 16 KB
    __shared__ float2 Zs[CC][MM];      // 6 KB
    __shared__ float  ct[256];
    int t = threadIdx.x;
    ct[t] = g_ctab[t];

    for (int idx = t; idx < CC * 64; idx += 256) {
        int i = idx >> 6, ww = idx & 63;
        xs[i][ww] = x[(((size_t)(b * CC + i)) * HH + h) * WW + wq * 64 + ww];
    }
    for (int idx = t; idx < CC * 16; idx += 256) {
        int o = idx >> 4, i4 = idx & 15;
        wcs[o][i4] = ((const float4*)wc)[o * 16 + i4];
    }
    {
        float2* zl = &Zs[0][0];
        const float2* zg = g_Z + (size_t)(b * HH + h) * (CC * MM);
        for (int idx = t; idx < CC * MM; idx += 256) zl[idx] = zg[idx];
    }
    __syncthreads();

    int w  = t & 63;
    int ty = t >> 6;                 // 0..3
    int wg = wq * 64 + w;

    // per-thread w twiddles (with Hermitian weight folded: ky=0 -> 1, else 2)
    float c2[MM], s2[MM];
    {
        int m = 0;
#pragma unroll
        for (int ky = 0; ky < MM; ky++) {
            float f = (ky == 0) ? 1.f : 2.f;
            c2[ky] = ct[m] * f;
            s2[ky] = ct[SIDX(m)] * f;
            m = (m + wg) & 255;
        }
    }

    float acc[16];
#pragma unroll
    for (int oo = 0; oo < 16; oo++) {
        int o = ty + 4 * oo;
        float a = bc[o];
#pragma unroll
        for (int ky = 0; ky < MM; ky++) {
            float2 z = Zs[o][ky];
            a = fmaf(z.x,  c2[ky], a);
            a = fmaf(-z.y, s2[ky], a);
        }
        acc[oo] = a;
    }

    // 1x1 conv: acc[o] += sum_i x[i] * wc[o][i]
#pragma unroll 4
    for (int i4 = 0; i4 < 16; i4++) {
        float xv0 = xs[i4 * 4 + 0][w];
        float xv1 = xs[i4 * 4 + 1][w];
        float xv2 = xs[i4 * 4 + 2][w];
        float xv3 = xs[i4 * 4 + 3][w];
#pragma unroll
        for (int oo = 0; oo < 16; oo++) {
            int o = ty + 4 * oo;
            float4 wv = wcs[o][i4];
            acc[oo] = fmaf(xv0, wv.x, acc[oo]);
            acc[oo] = fmaf(xv1, wv.y, acc[oo]);
            acc[oo] = fmaf(xv2, wv.z, acc[oo]);
            acc[oo] = fmaf(xv3, wv.w, acc[oo]);
        }
    }

#pragma unroll
    for (int oo = 0; oo < 16; oo++) {
        int o = ty + 4 * oo;
        out[(((size_t)(b * CC + o)) * HH + h) * WW + wg] = acc[oo];
    }
}

// ---------------- K6: per-channel sum / sumsq over y ----------------
__global__ void __launch_bounds__(256) k_stats(const float* __restrict__ y) {
    int bi = blockIdx.x;             // b*C + c plane
    int c  = bi & 63;
    const float* p = y + (size_t)bi * (HH * WW);
    float s = 0.f, q = 0.f;
#pragma unroll 4
    for (int idx = threadIdx.x; idx < HH * WW; idx += 256) {
        float v = p[idx];
        s += v;
        q = fmaf(v, v, q);
    }
    for (int o = 16; o > 0; o >>= 1) {
        s += __shfl_xor_sync(0xffffffffu, s, o);
        q += __shfl_xor_sync(0xffffffffu, q, o);
    }
    __shared__ float ss[8], qq[8];
    int wid = threadIdx.x >> 5, lid = threadIdx.x & 31;
    if (lid == 0) { ss[wid] = s; qq[wid] = q; }
    __syncthreads();
    if (threadIdx.x == 0) {
        float S = 0.f, Q = 0.f;
        for (int i = 0; i < 8; i++) { S += ss[i]; Q += qq[i]; }
        atomicAdd(&g_sum[c], S);
        atomicAdd(&g_sumsq[c], Q);
    }
}

// ---------------- K7: BN (batch stats, biased var) + exact GELU, in place ----------------
__global__ void __launch_bounds__(256) k_norm(const float* __restrict__ gamma,
                                              const float* __restrict__ beta,
                                              float* __restrict__ y) {
    int bi = blockIdx.x;
    int c  = bi & 63;
    const float invN = 1.0f / (float)(BB * HH * WW);
    float mean = g_sum[c] * invN;
    float var  = fmaf(-mean, mean, g_sumsq[c] * invN);
    float inv  = rsqrtf(var + 1e-5f);
    float ga = gamma[c] * inv;
    float bb = fmaf(-mean, ga, beta[c]);

    float* p = y + (size_t)bi * (HH * WW);
#pragma unroll 4
    for (int idx = threadIdx.x; idx < HH * WW; idx += 256) {
        float v = fmaf(p[idx], ga, bb);
        p[idx] = 0.5f * v * (1.0f + erff(v * 0.70710678118654752f));
    }
}

// ---------------- launch ----------------
extern "C" void kernel_launch(void* const* d_in, const int* in_sizes, int n_in,
                              void* d_out, int out_size) {
    const float* x     = (const float*)d_in[0];
    const float* w1    = (const float*)d_in[1];
    const float* w2    = (const float*)d_in[2];
    const float* wc    = (const float*)d_in[3];
    const float* bc    = (const float*)d_in[4];
    const float* gamma = (const float*)d_in[5];
    const float* beta  = (const float*)d_in[6];
    float* out = (float*)d_out;

    k_init<<<1, 256>>>();
    k_dft_h<<<NBI, 256>>>(x);
    k_dft_w<<<NBI, NPAIR>>>();
    k_mix<<<NPAIR, 256>>>(w1, w2);
    k_inv_h<<<NBI, 256>>>();
    k_final<<<dim3(4, HH, BB), 256>>>(x, wc, bc, out);
    k_stats<<<NBI, 256>>>(out);
    k_norm<<<NBI, 256>>>(gamma, beta, out);
}

// round 6
// speedup vs baseline: 1.3492x; 1.3492x over previous
#include <cuda_runtime.h>
#include <cstdint>
#include <cstddef>

// Problem constants
#define BB 16
#define CC 64
#define HH 256
#define WW 256
#define MM 12
#define NBI (BB*CC)          // 1024
#define NPAIR (24*MM)        // 288

typedef unsigned long long u64;

// ---------- f32x2 packed helpers (sm_100+ PTX) ----------
__device__ __forceinline__ u64 pack2(float lo, float hi) {
    u64 r; asm("mov.b64 %0, {%1,%2};" : "=l"(r) : "f"(lo), "f"(hi)); return r;
}
__device__ __forceinline__ void unpack2(u64 v, float& lo, float& hi) {
    asm("mov.b64 {%0,%1}, %2;" : "=f"(lo), "=f"(hi) : "l"(v));
}
__device__ __forceinline__ u64 fma2(u64 a, u64 b, u64 c) {
    u64 d; asm("fma.rn.f32x2 %0,%1,%2,%3;" : "=l"(d) : "l"(a), "l"(b), "l"(c)); return d;
}
__device__ __forceinline__ u64 add2(u64 a, u64 b) {
    u64 d; asm("add.rn.f32x2 %0,%1,%2;" : "=l"(d) : "l"(a), "l"(b)); return d;
}
__device__ __forceinline__ u64 neg2(u64 a) { return a ^ 0x8000000080000000ULL; }

// ---------------- device scratch ----------------
__device__ float2 g_Xh[(size_t)NBI * 13 * WW];          // h-DFT, k=0..12        (~27 MB)
__device__ float2 g_Xf[(size_t)NPAIR * NBI];            // modes [pair][b*C+i]
__device__ float2 g_Yf[(size_t)NBI * NPAIR];            // mixed [b*C+o][pair]
__device__ float2 g_Z[(size_t)BB * HH * MM * CC];       // [b][h][ky][o]         (~25 MB)
__device__ float2 g_Wt[(size_t)NPAIR * CC * CC];        // transposed spectral weights (~9.4 MB)
__device__ float  g_wcT[CC * CC];                       // transposed 1x1 conv weights
__device__ float  g_ctab[256];
__device__ float  g_sum[CC], g_sumsq[CC];

#define SIDX(m) (((m) + 192) & 255)

// ---------------- init: twiddles, stats, wc transpose ----------------
__global__ void k_init(const float* __restrict__ wc) {
    int t = threadIdx.x;
    g_ctab[t] = cospif((float)t * (1.0f / 128.0f));
    if (t < CC) { g_sum[t] = 0.f; g_sumsq[t] = 0.f; }
    for (int r = 0; r < 16; r++) {
        int idx = t + r * 256;                 // idx = o*64 + i (coalesced read)
        int o = idx >> 6, i = idx & 63;
        g_wcT[i * CC + o] = wc[idx];
    }
}

// ---------------- K0: transpose spectral weights -> [pair][i][o] float2 ----------------
__global__ void __launch_bounds__(256) k_wt(const float* __restrict__ w1,
                                            const float* __restrict__ w2) {
    int pair = blockIdx.x;
    int kxidx = pair / MM, ky = pair % MM;
    const float* wsrc = (kxidx < 12) ? w1 : w2;
    int kxrel = (kxidx < 12) ? kxidx : (kxidx - 12);
    size_t wbase = (size_t)(kxrel * MM + ky) * 2;
    float2* dst = g_Wt + (size_t)pair * (CC * CC);
    for (int idx = threadIdx.x; idx < CC * CC; idx += 256) {
        int i = idx >> 6, o = idx & 63;
        size_t off = (size_t)i * (CC * MM * MM * 2) + (size_t)o * (MM * MM * 2) + wbase;
        dst[idx] = make_float2(wsrc[off], wsrc[off + 1]);
    }
}

// ---------------- K1: h-DFT, k=0..12, f32x2 packed over w-pairs ----------------
__global__ void __launch_bounds__(128) k_dft_h(const float* __restrict__ x) {
    int bi = blockIdx.x;
    int w2 = threadIdx.x;                       // w-pair index 0..127
    __shared__ ulonglong2 tw[13 * 128];         // (c,c | s,s)  26 KB
    for (int idx = w2; idx < 13 * 128; idx += 128) {
        int k = idx >> 7, hh = idx & 127;
        int m = (k * hh) & 255;
        float c = cospif((float)m * (1.0f / 128.0f));
        float s = cospif((float)SIDX(m) * (1.0f / 128.0f));
        tw[idx] = make_ulonglong2(pack2(c, c), pack2(s, s));
    }
    __syncthreads();

    const u64* xq = (const u64*)(x + (size_t)bi * (HH * WW)) + w2;   // row stride 128 u64
    u64 x0   = xq[0];
    u64 x128 = xq[128 * 128];
    u64 nx128 = neg2(x128);

    u64 aR[13], aI[13];
#pragma unroll
    for (int k = 0; k < 13; k++) {
        aR[k] = add2(x0, (k & 1) ? nx128 : x128);
        aI[k] = 0ULL;
    }
#pragma unroll 2
    for (int h = 1; h < 128; h++) {
        u64 xa = xq[(size_t)h * 128];
        u64 xb = xq[(size_t)(256 - h) * 128];
        u64 sm = add2(xa, xb);
        u64 nd = add2(xb, neg2(xa));            // -(xa - xb)
#pragma unroll
        for (int k = 0; k < 13; k++) {
            ulonglong2 tt = tw[k * 128 + h];
            aR[k] = fma2(sm, tt.x, aR[k]);
            aI[k] = fma2(nd, tt.y, aI[k]);
        }
    }
    float4* go = (float4*)g_Xh;
#pragma unroll
    for (int k = 0; k < 13; k++) {
        float r0, r1, i0, i1;
        unpack2(aR[k], r0, r1); unpack2(aI[k], i0, i1);
        go[(size_t)(bi * 13 + k) * 128 + w2] = make_float4(r0, i0, r1, i1);
    }
}

// ---------------- K2: w-DFT to ky=0..11 for 24 kx rows ----------------
__global__ void __launch_bounds__(NPAIR) k_dft_w() {
    int bi = blockIdx.x;
    __shared__ float2 Xs[13 * WW];   // 26 KB
    __shared__ float  ct[256];
    int t = threadIdx.x;
    for (int idx = t; idx < 13 * WW; idx += NPAIR)
        Xs[idx] = g_Xh[(size_t)bi * 13 * WW + idx];
    if (t < 256) ct[t] = g_ctab[t];
    __syncthreads();

    int kxidx = t / MM, ky = t % MM;
    bool bot = (kxidx >= 12);
    int  krow = bot ? (24 - kxidx) : kxidx;
    float sgn = bot ? -1.f : 1.f;

    float aR = 0.f, aI = 0.f;
    int m = 0;
    for (int w = 0; w < WW; w++) {
        float2 v  = Xs[krow * WW + w];
        float  vi = v.y * sgn;
        float c = ct[m];
        float s = ct[SIDX(m)];
        aR = fmaf(v.x, c, aR); aR = fmaf(vi,  s, aR);
        aI = fmaf(vi,  c, aI); aI = fmaf(-v.x, s, aI);
        m = (m + ky) & 255;
    }
    g_Xf[(size_t)t * NBI + bi] = make_float2(aR, aI);
}

// ---------------- K3: channel mixing, f32x2 over batch pairs ----------------
__global__ void __launch_bounds__(256) k_mix() {
    int pair = blockIdx.x;
    __shared__ __align__(16) float AsR[CC * BB];   // [i][b]
    __shared__ __align__(16) float AsI[CC * BB];
    __shared__ float2 Ws[CC * CC];                 // [i][o]  32 KB
    int t = threadIdx.x;

    for (int idx = t; idx < BB * CC; idx += 256) {  // idx = b*64 + i
        int b = idx >> 6, i = idx & 63;
        float2 v = g_Xf[(size_t)pair * NBI + idx];
        AsR[i * BB + b] = v.x;
        AsI[i * BB + b] = v.y;
    }
    for (int idx = t; idx < CC * CC; idx += 256)
        Ws[idx] = g_Wt[(size_t)pair * (CC * CC) + idx];
    __syncthreads();

    int o  = t & 63;
    int bq = t >> 6;                 // 0..3 -> batches bq*4 .. bq*4+3 (2 pairs)
    const u64* AR = (const u64*)AsR;
    const u64* AI = (const u64*)AsI;
    int base = bq * 2;

    u64 aR0 = 0, aI0 = 0, aR1 = 0, aI1 = 0;
#pragma unroll 8
    for (int i = 0; i < CC; i++) {
        float2 wv = Ws[i * CC + o];
        u64 wr2 = pack2(wv.x, wv.x);
        u64 wi2 = pack2(wv.y, wv.y);
        u64 nwi2 = neg2(wi2);
        u64 r0 = AR[i * 8 + base],     r1 = AR[i * 8 + base + 1];
        u64 i0 = AI[i * 8 + base],     i1 = AI[i * 8 + base + 1];
        aR0 = fma2(r0, wr2, aR0); aR0 = fma2(i0, nwi2, aR0);
        aI0 = fma2(r0, wi2, aI0); aI0 = fma2(i0, wr2,  aI0);
        aR1 = fma2(r1, wr2, aR1); aR1 = fma2(i1, nwi2, aR1);
        aI1 = fma2(r1, wi2, aI1); aI1 = fma2(i1, wr2,  aI1);
    }
    float r0, r1, i0, i1;
    unpack2(aR0, r0, r1); unpack2(aI0, i0, i1);
    g_Yf[((size_t)((bq * 4 + 0) * CC + o)) * NPAIR + pair] = make_float2(r0, i0);
    g_Yf[((size_t)((bq * 4 + 1) * CC + o)) * NPAIR + pair] = make_float2(r1, i1);
    unpack2(aR1, r0, r1); unpack2(aI1, i0, i1);
    g_Yf[((size_t)((bq * 4 + 2) * CC + o)) * NPAIR + pair] = make_float2(r0, i0);
    g_Yf[((size_t)((bq * 4 + 3) * CC + o)) * NPAIR + pair] = make_float2(r1, i1);
}

// ---------------- K4: inverse h-DFT, f32x2 over ky-pairs; folds 1/(H*W), Hermitian x2, -Im ----------------
__global__ void __launch_bounds__(256) k_inv_h() {
    int bi = blockIdx.x;
    int b = bi >> 6, o = bi & 63;
    __shared__ __align__(16) float YsR[NPAIR], YsI[NPAIR];
    __shared__ float ct[256];
    int h = threadIdx.x;
    for (int idx = h; idx < NPAIR; idx += 256) {
        float2 v = g_Yf[(size_t)bi * NPAIR + idx];
        YsR[idx] = v.x; YsI[idx] = v.y;
    }
    ct[h] = g_ctab[h];
    __syncthreads();

    float cc[13], ss[13];
    {
        int m = 0;
#pragma unroll
        for (int k = 0; k < 13; k++) { cc[k] = ct[m]; ss[k] = ct[SIDX(m)]; m = (m + h) & 255; }
    }
    u64 aR[6] = {0,0,0,0,0,0}, aI[6] = {0,0,0,0,0,0};
    const u64* YR = (const u64*)YsR;
    const u64* YI = (const u64*)YsI;

#pragma unroll
    for (int k = 0; k < 12; k++) {               // top kx = k : e^{+ik th}
        u64 c2 = pack2(cc[k], cc[k]);
        u64 s2 = pack2(ss[k], ss[k]);
        u64 ns2 = neg2(s2);
#pragma unroll
        for (int p = 0; p < 6; p++) {
            u64 rp = YR[k * 6 + p], ip = YI[k * 6 + p];
            aR[p] = fma2(rp, c2, aR[p]); aR[p] = fma2(ip, ns2, aR[p]);
            aI[p] = fma2(rp, s2, aI[p]); aI[p] = fma2(ip, c2,  aI[p]);
        }
    }
#pragma unroll
    for (int mm = 0; mm < 12; mm++) {            // bottom kx = 244+mm : e^{-i(12-mm) th}
        u64 c2 = pack2(cc[12 - mm], cc[12 - mm]);
        u64 s2 = pack2(ss[12 - mm], ss[12 - mm]);
        u64 ns2 = neg2(s2);
#pragma unroll
        for (int p = 0; p < 6; p++) {
            u64 rp = YR[(12 + mm) * 6 + p], ip = YI[(12 + mm) * 6 + p];
            aR[p] = fma2(rp, c2, aR[p]); aR[p] = fma2(ip, s2,  aR[p]);
            aI[p] = fma2(ip, c2, aI[p]); aI[p] = fma2(rp, ns2, aI[p]);
        }
    }
    float2* zg = g_Z + (size_t)(b * HH + h) * (MM * CC);   // [ky][o]
    const float sc1 = 1.0f / 65536.0f, sc2 = 2.0f / 65536.0f;
#pragma unroll
    for (int p = 0; p < 6; p++) {
        float r0, r1, i0, i1;
        unpack2(aR[p], r0, r1); unpack2(aI[p], i0, i1);
        float s0 = (p == 0) ? sc1 : sc2;
        zg[(2 * p) * CC + o]     = make_float2(r0 * s0,  -(i0 * s0));
        zg[(2 * p + 1) * CC + o] = make_float2(r1 * sc2, -(i1 * sc2));
    }
}

// ---------------- K5: fused w-inverse + 1x1 conv + bias + stats -> y ----------------
// grid (4, 256, 16), 256 threads; thread = (ow 0..15 -> 4 o's, wg4 0..15 -> 4 w's)
__global__ void __launch_bounds__(256) k_final(const float* __restrict__ x,
                                               const float* __restrict__ bc,
                                               float* __restrict__ out) {
    int wq = blockIdx.x, h = blockIdx.y, b = blockIdx.z;
    __shared__ __align__(16) float xs[CC * 64];       // [i][w]   16 KB
    __shared__ __align__(16) float wcT[CC * CC];      // [i][o]   16 KB
    __shared__ float ZsR[MM * CC], ZsI[MM * CC];      // [ky][o]  6 KB
    __shared__ ulonglong2 twc[MM * 32];               // (c,c|s,s)[ky][wpair] 6 KB (aliased as red)
    float* red = (float*)twc;                         // reused after conv: [warp][o][2] 4 KB
    int t = threadIdx.x;
    int ow = t & 15, wg4 = t >> 4;

    // loads
    {
        int i = t >> 4, wg = t & 15;
#pragma unroll
        for (int r = 0; r < 4; r++) {
            int ii = i + r * 16;
            ((float4*)xs)[ii * 16 + wg] =
                ((const float4*)(x + (((size_t)(b * CC + ii)) * HH + h) * WW + wq * 64))[wg];
        }
    }
#pragma unroll
    for (int r = 0; r < 4; r++) {
        int idx = t + r * 256;
        ((float4*)wcT)[idx] = ((const float4*)g_wcT)[idx];
    }
    {
        const float2* zg = g_Z + (size_t)(b * HH + h) * (MM * CC);
#pragma unroll
        for (int r = 0; r < 3; r++) {
            int idx = t + r * 256;                  // idx = ky*64 + o
            float2 v = zg[idx];
            ZsR[idx] = v.x; ZsI[idx] = v.y;
        }
    }
#pragma unroll
    for (int r = 0; r < 2; r++) {
        int idx = t + r * 256;
        if (idx < MM * 32) {
            int ky = idx >> 5, wp = idx & 31;
            int w0 = wq * 64 + wp * 2;
            int m0 = (ky * w0) & 255;
            int m1 = (ky * (w0 + 1)) & 255;
            float c0 = cospif((float)m0 * (1.0f / 128.0f));
            float c1 = cospif((float)m1 * (1.0f / 128.0f));
            float s0 = cospif((float)SIDX(m0) * (1.0f / 128.0f));
            float s1 = cospif((float)SIDX(m1) * (1.0f / 128.0f));
            twc[idx] = make_ulonglong2(pack2(c0, c1), pack2(s0, s1));
        }
    }
    __syncthreads();

    // accumulators: acc[q][wp]  (q -> o = ow*4+q ; wp -> w-pair)
    u64 acc[4][2];
#pragma unroll
    for (int q = 0; q < 4; q++) {
        float bb = bc[ow * 4 + q];
        acc[q][0] = pack2(bb, bb);
        acc[q][1] = acc[q][0];
    }

    // spectral: y += Re(z)*cos + (-Im(z))*sin   (signs/2x/scale folded in k_inv_h)
#pragma unroll 4
    for (int ky = 0; ky < MM; ky++) {
        ulonglong2 t0 = twc[ky * 32 + wg4 * 2];
        ulonglong2 t1 = twc[ky * 32 + wg4 * 2 + 1];
#pragma unroll
        for (int q = 0; q < 4; q++) {
            float zr = ZsR[ky * CC + ow * 4 + q];
            float zi = ZsI[ky * CC + ow * 4 + q];
            u64 zr2 = pack2(zr, zr), zi2 = pack2(zi, zi);
            acc[q][0] = fma2(zr2, t0.x, acc[q][0]); acc[q][0] = fma2(zi2, t0.y, acc[q][0]);
            acc[q][1] = fma2(zr2, t1.x, acc[q][1]); acc[q][1] = fma2(zi2, t1.y, acc[q][1]);
        }
    }

    // 1x1 conv GEMM
    {
        const float4* wc4 = (const float4*)wcT;
        const float4* xsc = (const float4*)xs;
#pragma unroll 8
        for (int i = 0; i < CC; i++) {
            float4 av = wc4[i * 16 + ow];
            float4 bv = xsc[i * 16 + wg4];
            u64 b01 = pack2(bv.x, bv.y), b23 = pack2(bv.z, bv.w);
            u64 a0 = pack2(av.x, av.x);
            u64 a1 = pack2(av.y, av.y);
            u64 a2 = pack2(av.z, av.z);
            u64 a3 = pack2(av.w, av.w);
            acc[0][0] = fma2(a0, b01, acc[0][0]); acc[0][1] = fma2(a0, b23, acc[0][1]);
            acc[1][0] = fma2(a1, b01, acc[1][0]); acc[1][1] = fma2(a1, b23, acc[1][1]);
            acc[2][0] = fma2(a2, b01, acc[2][0]); acc[2][1] = fma2(a2, b23, acc[2][1]);
            acc[3][0] = fma2(a3, b01, acc[3][0]); acc[3][1] = fma2(a3, b23, acc[3][1]);
        }
    }

    __syncthreads();   // protect twc->red alias

    // store + per-channel stats
    size_t pix = (size_t)h * WW + wq * 64 + wg4 * 4;
    int warp = t >> 5;
#pragma unroll
    for (int q = 0; q < 4; q++) {
        int o = ow * 4 + q;
        float v0, v1, v2, v3;
        unpack2(acc[q][0], v0, v1); unpack2(acc[q][1], v2, v3);
        *(float4*)(out + (size_t)(b * CC + o) * (HH * WW) + pix) = make_float4(v0, v1, v2, v3);
        float s = (v0 + v1) + (v2 + v3);
        float qq = v0 * v0; qq = fmaf(v1, v1, qq); qq = fmaf(v2, v2, qq); qq = fmaf(v3, v3, qq);
        s  += __shfl_xor_sync(0xffffffffu, s, 16);
        qq += __shfl_xor_sync(0xffffffffu, qq, 16);
        if ((t & 31) < 16) {
            red[warp * 128 + o * 2]     = s;
            red[warp * 128 + o * 2 + 1] = qq;
        }
    }
    __syncthreads();
    if (t < CC) {
        float S = 0.f, Q = 0.f;
#pragma unroll
        for (int wp = 0; wp < 8; wp++) {
            S += red[wp * 128 + t * 2];
            Q += red[wp * 128 + t * 2 + 1];
        }
        atomicAdd(&g_sum[t], S);
        atomicAdd(&g_sumsq[t], Q);
    }
}

// ---------------- K6: BN (batch stats, biased var) + exact GELU, in place ----------------
__global__ void __launch_bounds__(256) k_norm(const float* __restrict__ gamma,
                                              const float* __restrict__ beta,
                                              float* __restrict__ y) {
    int bi = blockIdx.x;
    int c  = bi & 63;
    const float invN = 1.0f / (float)(BB * HH * WW);
    float mean = g_sum[c] * invN;
    float var  = fmaf(-mean, mean, g_sumsq[c] * invN);
    float inv  = rsqrtf(var + 1e-5f);
    float ga = gamma[c] * inv;
    float bb = fmaf(-mean, ga, beta[c]);

    float4* p = (float4*)(y + (size_t)bi * (HH * WW));
#pragma unroll 2
    for (int idx = threadIdx.x; idx < (HH * WW) / 4; idx += 256) {
        float4 v = p[idx];
        float a0 = fmaf(v.x, ga, bb);
        float a1 = fmaf(v.y, ga, bb);
        float a2 = fmaf(v.z, ga, bb);
        float a3 = fmaf(v.w, ga, bb);
        v.x = 0.5f * a0 * (1.0f + erff(a0 * 0.70710678118654752f));
        v.y = 0.5f * a1 * (1.0f + erff(a1 * 0.70710678118654752f));
        v.z = 0.5f * a2 * (1.0f + erff(a2 * 0.70710678118654752f));
        v.w = 0.5f * a3 * (1.0f + erff(a3 * 0.70710678118654752f));
        p[idx] = v;
    }
}

// ---------------- launch ----------------
extern "C" void kernel_launch(void* const* d_in, const int* in_sizes, int n_in,
                              void* d_out, int out_size) {
    const float* x     = (const float*)d_in[0];
    const float* w1    = (const float*)d_in[1];
    const float* w2    = (const float*)d_in[2];
    const float* wc    = (const float*)d_in[3];
    const float* bc    = (const float*)d_in[4];
    const float* gamma = (const float*)d_in[5];
    const float* beta  = (const float*)d_in[6];
    float* out = (float*)d_out;

    k_init<<<1, 256>>>(wc);
    k_wt<<<NPAIR, 256>>>(w1, w2);
    k_dft_h<<<NBI, 128>>>(x);
    k_dft_w<<<NBI, NPAIR>>>();
    k_mix<<<NPAIR, 256>>>();
    k_inv_h<<<NBI, 256>>>();
    k_final<<<dim3(4, HH, BB), 256>>>(x, bc, out);
    k_norm<<<NBI, 256>>>(gamma, beta, out);
}

// round 9
// speedup vs baseline: 1.5263x; 1.1312x over previous
#include <cuda_runtime.h>
#include <cstdint>
#include <cstddef>

// Problem constants
#define BB 16
#define CC 64
#define HH 256
#define WW 256
#define MM 12
#define NBI (BB*CC)          // 1024
#define NPAIR (24*MM)        // 288

typedef unsigned long long u64;

// ---------- f32x2 packed helpers (sm_100+ PTX) ----------
__device__ __forceinline__ u64 pack2(float lo, float hi) {
    u64 r; asm("mov.b64 %0, {%1,%2};" : "=l"(r) : "f"(lo), "f"(hi)); return r;
}
__device__ __forceinline__ void unpack2(u64 v, float& lo, float& hi) {
    asm("mov.b64 {%0,%1}, %2;" : "=f"(lo), "=f"(hi) : "l"(v));
}
__device__ __forceinline__ u64 fma2(u64 a, u64 b, u64 c) {
    u64 d; asm("fma.rn.f32x2 %0,%1,%2,%3;" : "=l"(d) : "l"(a), "l"(b), "l"(c)); return d;
}
__device__ __forceinline__ u64 add2(u64 a, u64 b) {
    u64 d; asm("add.rn.f32x2 %0,%1,%2;" : "=l"(d) : "l"(a), "l"(b)); return d;
}
__device__ __forceinline__ u64 neg2(u64 a) { return a ^ 0x8000000080000000ULL; }

// ---------------- device scratch ----------------
__device__ float2 g_Xh[(size_t)NBI * 13 * WW];          // h-DFT, k=0..12        (~27 MB)
__device__ float2 g_Xf[(size_t)NPAIR * NBI];            // modes [pair][b*C+i]
__device__ float2 g_Yf[(size_t)NBI * NPAIR];            // mixed [b*C+o][pair]
__device__ float2 g_Z[(size_t)BB * HH * MM * CC];       // [b][h][ky][o]         (~25 MB)
__device__ float2 g_Wt[(size_t)NPAIR * CC * CC];        // transposed spectral weights (~9.4 MB)
__device__ float  g_wcT[CC * CC];                       // transposed 1x1 conv weights
__device__ float  g_ctab[256];
__device__ float  g_sum[CC], g_sumsq[CC];

#define SIDX(m) (((m) + 192) & 255)

// ---------------- init: twiddles, stats, wc transpose ----------------
__global__ void k_init(const float* __restrict__ wc) {
    int t = threadIdx.x;
    g_ctab[t] = cospif((float)t * (1.0f / 128.0f));
    if (t < CC) { g_sum[t] = 0.f; g_sumsq[t] = 0.f; }
    for (int r = 0; r < 16; r++) {
        int idx = t + r * 256;                 // idx = o*64 + i (coalesced read)
        int o = idx >> 6, i = idx & 63;
        g_wcT[i * CC + o] = wc[idx];
    }
}

// ---------------- K0: transpose spectral weights -> [pair][i][o] float2 ----------------
__global__ void __launch_bounds__(256) k_wt(const float* __restrict__ w1,
                                            const float* __restrict__ w2) {
    int pair = blockIdx.x;
    int kxidx = pair / MM, ky = pair % MM;
    const float* wsrc = (kxidx < 12) ? w1 : w2;
    int kxrel = (kxidx < 12) ? kxidx : (kxidx - 12);
    size_t wbase = (size_t)(kxrel * MM + ky) * 2;
    float2* dst = g_Wt + (size_t)pair * (CC * CC);
    for (int idx = threadIdx.x; idx < CC * CC; idx += 256) {
        int i = idx >> 6, o = idx & 63;
        size_t off = (size_t)i * (CC * MM * MM * 2) + (size_t)o * (MM * MM * 2) + wbase;
        dst[idx] = make_float2(wsrc[off], wsrc[off + 1]);
    }
}

// ---------------- K1: h-DFT, k=0..12, f32x2 over w-pairs, quad h-symmetry ----------------
// Uses h <-> 256-h AND h <-> 128-h:  cos(k*(pi-th)) = (-1)^k cos(k th),
//                                    sin(k*(pi-th)) = -(-1)^k sin(k th)
__global__ void __launch_bounds__(128) k_dft_h(const float* __restrict__ x) {
    int bi = blockIdx.x;
    int w2 = threadIdx.x;                       // w-pair index 0..127
    __shared__ ulonglong2 tw[13 * 64];          // (c,c | s,s) for h=1..63   13 KB
    for (int idx = w2; idx < 13 * 64; idx += 128) {
        int k = idx >> 6, hh = idx & 63;
        int m = (k * hh) & 255;
        float c = cospif((float)m * (1.0f / 128.0f));
        float s = cospif((float)SIDX(m) * (1.0f / 128.0f));
        tw[idx] = make_ulonglong2(pack2(c, c), pack2(s, s));
    }
    __syncthreads();

    const u64* xq = (const u64*)(x + (size_t)bi * (HH * WW)) + w2;   // row stride 128 u64
    u64 x0   = xq[0];
    u64 x128 = xq[(size_t)128 * 128];
    u64 nx128 = neg2(x128);

    u64 aR[13], aI[13];
#pragma unroll
    for (int k = 0; k < 13; k++) {
        aR[k] = add2(x0, (k & 1) ? nx128 : x128);
        aI[k] = 0ULL;
    }
    // h = 64 special: theta = pi/2 -> cos(k pi/2) in {1,0,-1,0}, sin in {0,1,0,-1}
    {
        u64 a = xq[(size_t)64 * 128], b = xq[(size_t)192 * 128];
        u64 sm = add2(a, b);
        u64 df = add2(a, neg2(b));
        u64 nsm = neg2(sm), ndf = neg2(df);
        aR[0] = add2(aR[0], sm);  aR[4]  = add2(aR[4], sm);
        aR[8] = add2(aR[8], sm);  aR[12] = add2(aR[12], sm);
        aR[2] = add2(aR[2], nsm); aR[6]  = add2(aR[6], nsm); aR[10] = add2(aR[10], nsm);
        aI[1] = add2(aI[1], ndf); aI[5]  = add2(aI[5], ndf); aI[9]  = add2(aI[9], ndf);
        aI[3] = add2(aI[3], df);  aI[7]  = add2(aI[7], df);  aI[11] = add2(aI[11], df);
    }
#pragma unroll 4
    for (int h = 1; h < 64; h++) {
        u64 xa = xq[(size_t)h * 128];
        u64 xb = xq[(size_t)(256 - h) * 128];
        u64 xc = xq[(size_t)(128 - h) * 128];
        u64 xd = xq[(size_t)(128 + h) * 128];
        u64 sm1 = add2(xa, xb), df1 = add2(xa, neg2(xb));
        u64 sm2 = add2(xc, xd), df2 = add2(xc, neg2(xd));
        u64 se  = add2(sm1, sm2);
        u64 so  = add2(sm1, neg2(sm2));
        u64 nde = add2(df2, neg2(df1));          // -(df1 - df2)  (even k imag)
        u64 ndo = neg2(add2(df1, df2));          // -(df1 + df2)  (odd  k imag)
#pragma unroll
        for (int k = 0; k < 13; k++) {
            ulonglong2 tt = tw[k * 64 + h];
            aR[k] = fma2((k & 1) ? so  : se,  tt.x, aR[k]);
            aI[k] = fma2((k & 1) ? ndo : nde, tt.y, aI[k]);
        }
    }
    float4* go = (float4*)g_Xh;
#pragma unroll
    for (int k = 0; k < 13; k++) {
        float r0, r1, i0, i1;
        unpack2(aR[k], r0, r1); unpack2(aI[k], i0, i1);
        go[(size_t)(bi * 13 + k) * 128 + w2] = make_float4(r0, i0, r1, i1);
    }
}

// ---------------- K2: w-DFT to ky=0..11; shared partial sums give top+bottom kx ----------------
// thread = (krow 0..12, ky 0..11). P=sum vr*c, Q=sum vy*s, R=sum vy*c, S=sum vr*s.
// top (kx=krow):      (P+Q,  R-S)
// bottom (kx=244+..): (P-Q, -R-S)   [conj of data row krow]
__global__ void __launch_bounds__(160) k_dft_w() {
    int bi = blockIdx.x;
    __shared__ float2 Xs[13 * 257];   // padded stride kills bank collisions  ~26.7 KB
    __shared__ float  ct[256];
    int t = threadIdx.x;
    for (int idx = t; idx < 13 * 256; idx += 160) {
        int r = idx >> 8, w = idx & 255;
        Xs[r * 257 + w] = g_Xh[(size_t)bi * (13 * 256) + idx];
    }
    for (int idx = t; idx < 256; idx += 160) ct[idx] = g_ctab[idx];
    __syncthreads();

    if (t < 156) {
        int krow = t / MM, ky = t - krow * MM;
        const float2* xr = Xs + krow * 257;
        float P = 0.f, Q = 0.f, R = 0.f, S = 0.f;
        int m = 0;
#pragma unroll 4
        for (int w = 0; w < WW; w++) {
            float2 v = xr[w];
            float c = ct[m];
            float s = ct[SIDX(m)];
            P = fmaf(v.x, c, P);
            S = fmaf(v.x, s, S);
            R = fmaf(v.y, c, R);
            Q = fmaf(v.y, s, Q);
            m = (m + ky) & 255;
        }
        if (krow < 12)
            g_Xf[(size_t)(krow * MM + ky) * NBI + bi] = make_float2(P + Q, R - S);
        if (krow > 0)
            g_Xf[(size_t)((24 - krow) * MM + ky) * NBI + bi] = make_float2(P - Q, -R - S);
    }
}

// ---------------- K3: channel mixing, f32x2 over batch pairs ----------------
__global__ void __launch_bounds__(256) k_mix() {
    int pair = blockIdx.x;
    __shared__ __align__(16) float AsR[CC * BB];   // [i][b]
    __shared__ __align__(16) float AsI[CC * BB];
    __shared__ float2 Ws[CC * CC];                 // [i][o]  32 KB
    int t = threadIdx.x;

    for (int idx = t; idx < BB * CC; idx += 256) {  // idx = b*64 + i
        int b = idx >> 6, i = idx & 63;
        float2 v = g_Xf[(size_t)pair * NBI + idx];
        AsR[i * BB + b] = v.x;
        AsI[i * BB + b] = v.y;
    }
    for (int idx = t; idx < CC * CC; idx += 256)
        Ws[idx] = g_Wt[(size_t)pair * (CC * CC) + idx];
    __syncthreads();

    int o  = t & 63;
    int bq = t >> 6;                 // 0..3 -> batches bq*4 .. bq*4+3 (2 pairs)
    const u64* AR = (const u64*)AsR;
    const u64* AI = (const u64*)AsI;
    int base = bq * 2;

    u64 aR0 = 0, aI0 = 0, aR1 = 0, aI1 = 0;
#pragma unroll 8
    for (int i = 0; i < CC; i++) {
        float2 wv = Ws[i * CC + o];
        u64 wr2 = pack2(wv.x, wv.x);
        u64 wi2 = pack2(wv.y, wv.y);
        u64 nwi2 = neg2(wi2);
        u64 r0 = AR[i * 8 + base],     r1 = AR[i * 8 + base + 1];
        u64 i0 = AI[i * 8 + base],     i1 = AI[i * 8 + base + 1];
        aR0 = fma2(r0, wr2, aR0); aR0 = fma2(i0, nwi2, aR0);
        aI0 = fma2(r0, wi2, aI0); aI0 = fma2(i0, wr2,  aI0);
        aR1 = fma2(r1, wr2, aR1); aR1 = fma2(i1, nwi2, aR1);
        aI1 = fma2(r1, wi2, aI1); aI1 = fma2(i1, wr2,  aI1);
    }
    float r0, r1, i0, i1;
    unpack2(aR0, r0, r1); unpack2(aI0, i0, i1);
    g_Yf[((size_t)((bq * 4 + 0) * CC + o)) * NPAIR + pair] = make_float2(r0, i0);
    g_Yf[((size_t)((bq * 4 + 1) * CC + o)) * NPAIR + pair] = make_float2(r1, i1);
    unpack2(aR1, r0, r1); unpack2(aI1, i0, i1);
    g_Yf[((size_t)((bq * 4 + 2) * CC + o)) * NPAIR + pair] = make_float2(r0, i0);
    g_Yf[((size_t)((bq * 4 + 3) * CC + o)) * NPAIR + pair] = make_float2(r1, i1);
}

// ---------------- K4: inverse h-DFT, f32x2 over ky-pairs; folds 1/(H*W), Hermitian x2, -Im ----------------
__global__ void __launch_bounds__(256) k_inv_h() {
    int bi = blockIdx.x;
    int b = bi >> 6, o = bi & 63;
    __shared__ __align__(16) float YsR[NPAIR], YsI[NPAIR];
    __shared__ float ct[256];
    int h = threadIdx.x;
    for (int idx = h; idx < NPAIR; idx += 256) {
        float2 v = g_Yf[(size_t)bi * NPAIR + idx];
        YsR[idx] = v.x; YsI[idx] = v.y;
    }
    ct[h] = g_ctab[h];
    __syncthreads();

    float cc[13], ss[13];
    {
        int m = 0;
#pragma unroll
        for (int k = 0; k < 13; k++) { cc[k] = ct[m]; ss[k] = ct[SIDX(m)]; m = (m + h) & 255; }
    }
    u64 aR[6] = {0,0,0,0,0,0}, aI[6] = {0,0,0,0,0,0};
    const u64* YR = (const u64*)YsR;
    const u64* YI = (const u64*)YsI;

#pragma unroll
    for (int k = 0; k < 12; k++) {               // top kx = k : e^{+ik th}
        u64 c2 = pack2(cc[k], cc[k]);
        u64 s2 = pack2(ss[k], ss[k]);
        u64 ns2 = neg2(s2);
#pragma unroll
        for (int p = 0; p < 6; p++) {
            u64 rp = YR[k * 6 + p], ip = YI[k * 6 + p];
            aR[p] = fma2(rp, c2, aR[p]); aR[p] = fma2(ip, ns2, aR[p]);
            aI[p] = fma2(rp, s2, aI[p]); aI[p] = fma2(ip, c2,  aI[p]);
        }
    }
#pragma unroll
    for (int mm = 0; mm < 12; mm++) {            // bottom kx = 244+mm : e^{-i(12-mm) th}
        u64 c2 = pack2(cc[12 - mm], cc[12 - mm]);
        u64 s2 = pack2(ss[12 - mm], ss[12 - mm]);
        u64 ns2 = neg2(s2);
#pragma unroll
        for (int p = 0; p < 6; p++) {
            u64 rp = YR[(12 + mm) * 6 + p], ip = YI[(12 + mm) * 6 + p];
            aR[p] = fma2(rp, c2, aR[p]); aR[p] = fma2(ip, s2,  aR[p]);
            aI[p] = fma2(ip, c2, aI[p]); aI[p] = fma2(rp, ns2, aI[p]);
        }
    }
    float2* zg = g_Z + (size_t)(b * HH + h) * (MM * CC);   // [ky][o]
    const float sc1 = 1.0f / 65536.0f, sc2 = 2.0f / 65536.0f;
#pragma unroll
    for (int p = 0; p < 6; p++) {
        float r0, r1, i0, i1;
        unpack2(aR[p], r0, r1); unpack2(aI[p], i0, i1);
        float s0 = (p == 0) ? sc1 : sc2;
        zg[(2 * p) * CC + o]     = make_float2(r0 * s0,  -(i0 * s0));
        zg[(2 * p + 1) * CC + o] = make_float2(r1 * sc2, -(i1 * sc2));
    }
}

// ---------------- K5: fused w-inverse + 1x1 conv + bias + stats -> y ----------------
// grid (4, 256, 16), 256 threads; thread = (ow 0..15 -> 4 o's, wg4 0..15 -> 4 w's)
__global__ void __launch_bounds__(256) k_final(const float* __restrict__ x,
                                               const float* __restrict__ bc,
                                               float* __restrict__ out) {
    int wq = blockIdx.x, h = blockIdx.y, b = blockIdx.z;
    __shared__ __align__(16) float xs[CC * 64];       // [i][w]   16 KB
    __shared__ __align__(16) float wcT[CC * CC];      // [i][o]   16 KB
    __shared__ float ZsR[MM * CC], ZsI[MM * CC];      // [ky][o]  6 KB
    __shared__ ulonglong2 twc[MM * 32];               // (c,c|s,s)[ky][wpair] 6 KB (aliased as red)
    float* red = (float*)twc;                         // reused after conv: [warp][o][2] 4 KB
    int t = threadIdx.x;
    int ow = t & 15, wg4 = t >> 4;

    // loads
    {
        int i = t >> 4, wg = t & 15;
#pragma unroll
        for (int r = 0; r < 4; r++) {
            int ii = i + r * 16;
            ((float4*)xs)[ii * 16 + wg] =
                ((const float4*)(x + (((size_t)(b * CC + ii)) * HH + h) * WW + wq * 64))[wg];
        }
    }
#pragma unroll
    for (int r = 0; r < 4; r++) {
        int idx = t + r * 256;
        ((float4*)wcT)[idx] = ((const float4*)g_wcT)[idx];
    }
    {
        const float2* zg = g_Z + (size_t)(b * HH + h) * (MM * CC);
#pragma unroll
        for (int r = 0; r < 3; r++) {
            int idx = t + r * 256;                  // idx = ky*64 + o
            float2 v = zg[idx];
            ZsR[idx] = v.x; ZsI[idx] = v.y;
        }
    }
#pragma unroll
    for (int r = 0; r < 2; r++) {
        int idx = t + r * 256;
        if (idx < MM * 32) {
            int ky = idx >> 5, wp = idx & 31;
            int w0 = wq * 64 + wp * 2;
            int m0 = (ky * w0) & 255;
            int m1 = (ky * (w0 + 1)) & 255;
            float c0 = cospif((float)m0 * (1.0f / 128.0f));
            float c1 = cospif((float)m1 * (1.0f / 128.0f));
            float s0 = cospif((float)SIDX(m0) * (1.0f / 128.0f));
            float s1 = cospif((float)SIDX(m1) * (1.0f / 128.0f));
            twc[idx] = make_ulonglong2(pack2(c0, c1), pack2(s0, s1));
        }
    }
    __syncthreads();

    // accumulators: acc[q][wp]  (q -> o = ow*4+q ; wp -> w-pair)
    u64 acc[4][2];
#pragma unroll
    for (int q = 0; q < 4; q++) {
        float bb = bc[ow * 4 + q];
        acc[q][0] = pack2(bb, bb);
        acc[q][1] = acc[q][0];
    }

    // spectral: y += Re(z)*cos + (-Im(z))*sin   (signs/2x/scale folded in k_inv_h)
#pragma unroll 4
    for (int ky = 0; ky < MM; ky++) {
        ulonglong2 t0 = twc[ky * 32 + wg4 * 2];
        ulonglong2 t1 = twc[ky * 32 + wg4 * 2 + 1];
#pragma unroll
        for (int q = 0; q < 4; q++) {
            float zr = ZsR[ky * CC + ow * 4 + q];
            float zi = ZsI[ky * CC + ow * 4 + q];
            u64 zr2 = pack2(zr, zr), zi2 = pack2(zi, zi);
            acc[q][0] = fma2(zr2, t0.x, acc[q][0]); acc[q][0] = fma2(zi2, t0.y, acc[q][0]);
            acc[q][1] = fma2(zr2, t1.x, acc[q][1]); acc[q][1] = fma2(zi2, t1.y, acc[q][1]);
        }
    }

    // 1x1 conv GEMM (b-operand type-punned: zero packs on the x side)
    {
        const float4*     wc4 = (const float4*)wcT;
        const ulonglong2* xsc = (const ulonglong2*)xs;
#pragma unroll 8
        for (int i = 0; i < CC; i++) {
            float4 av = wc4[i * 16 + ow];
            ulonglong2 bv = xsc[i * 16 + wg4];
            u64 b01 = bv.x, b23 = bv.y;
            u64 a0 = pack2(av.x, av.x);
            u64 a1 = pack2(av.y, av.y);
            u64 a2 = pack2(av.z, av.z);
            u64 a3 = pack2(av.w, av.w);
            acc[0][0] = fma2(a0, b01, acc[0][0]); acc[0][1] = fma2(a0, b23, acc[0][1]);
            acc[1][0] = fma2(a1, b01, acc[1][0]); acc[1][1] = fma2(a1, b23, acc[1][1]);
            acc[2][0] = fma2(a2, b01, acc[2][0]); acc[2][1] = fma2(a2, b23, acc[2][1]);
            acc[3][0] = fma2(a3, b01, acc[3][0]); acc[3][1] = fma2(a3, b23, acc[3][1]);
        }
    }

    __syncthreads();   // protect twc->red alias

    // store + per-channel stats
    size_t pix = (size_t)h * WW + wq * 64 + wg4 * 4;
    int warp = t >> 5;
#pragma unroll
    for (int q = 0; q < 4; q++) {
        int o = ow * 4 + q;
        float v0, v1, v2, v3;
        unpack2(acc[q][0], v0, v1); unpack2(acc[q][1], v2, v3);
        *(float4*)(out + (size_t)(b * CC + o) * (HH * WW) + pix) = make_float4(v0, v1, v2, v3);
        float s = (v0 + v1) + (v2 + v3);
        float qq = v0 * v0; qq = fmaf(v1, v1, qq); qq = fmaf(v2, v2, qq); qq = fmaf(v3, v3, qq);
        s  += __shfl_xor_sync(0xffffffffu, s, 16);
        qq += __shfl_xor_sync(0xffffffffu, qq, 16);
        if ((t & 31) < 16) {
            red[warp * 128 + o * 2]     = s;
            red[warp * 128 + o * 2 + 1] = qq;
        }
    }
    __syncthreads();
    if (t < CC) {
        float S = 0.f, Q = 0.f;
#pragma unroll
        for (int wp = 0; wp < 8; wp++) {
            S += red[wp * 128 + t * 2];
            Q += red[wp * 128 + t * 2 + 1];
        }
        atomicAdd(&g_sum[t], S);
        atomicAdd(&g_sumsq[t], Q);
    }
}

// ---------------- K6: BN (batch stats, biased var) + exact GELU, in place ----------------
__global__ void __launch_bounds__(256) k_norm(const float* __restrict__ gamma,
                                              const float* __restrict__ beta,
                                              float* __restrict__ y) {
    int bi = blockIdx.x;
    int c  = bi & 63;
    const float invN = 1.0f / (float)(BB * HH * WW);
    float mean = g_sum[c] * invN;
    float var  = fmaf(-mean, mean, g_sumsq[c] * invN);
    float inv  = rsqrtf(var + 1e-5f);
    float ga = gamma[c] * inv;
    float bb = fmaf(-mean, ga, beta[c]);

    float4* p = (float4*)(y + (size_t)bi * (HH * WW));
#pragma unroll 2
    for (int idx = threadIdx.x; idx < (HH * WW) / 4; idx += 256) {
        float4 v = p[idx];
        float a0 = fmaf(v.x, ga, bb);
        float a1 = fmaf(v.y, ga, bb);
        float a2 = fmaf(v.z, ga, bb);
        float a3 = fmaf(v.w, ga, bb);
        v.x = 0.5f * a0 * (1.0f + erff(a0 * 0.70710678118654752f));
        v.y = 0.5f * a1 * (1.0f + erff(a1 * 0.70710678118654752f));
        v.z = 0.5f * a2 * (1.0f + erff(a2 * 0.70710678118654752f));
        v.w = 0.5f * a3 * (1.0f + erff(a3 * 0.70710678118654752f));
        p[idx] = v;
    }
}

// ---------------- launch ----------------
extern "C" void kernel_launch(void* const* d_in, const int* in_sizes, int n_in,
                              void* d_out, int out_size) {
    const float* x     = (const float*)d_in[0];
    const float* w1    = (const float*)d_in[1];
    const float* w2    = (const float*)d_in[2];
    const float* wc    = (const float*)d_in[3];
    const float* bc    = (const float*)d_in[4];
    const float* gamma = (const float*)d_in[5];
    const float* beta  = (const float*)d_in[6];
    float* out = (float*)d_out;

    k_init<<<1, 256>>>(wc);
    k_wt<<<NPAIR, 256>>>(w1, w2);
    k_dft_h<<<NBI, 128>>>(x);
    k_dft_w<<<NBI, 160>>>();
    k_mix<<<NPAIR, 256>>>();
    k_inv_h<<<NBI, 256>>>();
    k_final<<<dim3(4, HH, BB), 256>>>(x, bc, out);
    k_norm<<<NBI, 256>>>(gamma, beta, out);
}